// round 6
// baseline (speedup 1.0000x reference)
#include <cuda_runtime.h>
#include <cuda_bf16.h>
#include <cstdint>
#include <cstddef>

// ---------------------------------------------------------------------------
// Problem constants
// ---------------------------------------------------------------------------
static constexpr int D_DIM  = 2496;   // 16*13*12
static constexpr int B_ROWS = 4096;
static constexpr int S_ROWS = 2048;

// INT8 quantization: q = round(254*x) - 127, x in [0,1).
// cross = (dot + 127*(rsx+rsm) + 127^2*D) / 254^2   (exact in s32)
// out   = a[b] + b[s] + dot * K_DOT
//   a[b] = -xsq[b]/500 + rsx[b]*K_RS + K_C
//   b[s] = -msq[s]/500 + rsm[s]*K_RS + K_C
static constexpr float K_DOT = 1.0f / 16129000.0f;          // 1/(254^2*250)
static constexpr float K_RS  = 127.0f / 16129000.0f;
static constexpr float K_C   = 1.248f;                       // 127^2*D/(254^2*250)/2

// GEMM tiling (legacy mma path; int8 m16n8k32)
static constexpr int BM = 128;            // batch rows per CTA (M)
static constexpr int BN = 256;            // states per CTA (N)
static constexpr int BK = 64;             // K elems (bytes) per stage
static constexpr int KITERS = D_DIM / BK; // 39 exact
static constexpr int STAGES = 4;
static constexpr int NTHREADS = 512;      // 16 warps: 4(M) x 4(N)

// Padded smem rows: 64 B data + 16 B pad = 80 B stride (conflict-free).
static constexpr int ROW_STRIDE  = 80;
static constexpr int A_ST_BYTES  = BM * ROW_STRIDE;          // 10240
static constexpr int B_ST_BYTES  = BN * ROW_STRIDE;          // 20480
static constexpr int STAGE_BYTES = A_ST_BYTES + B_ST_BYTES;  // 30720
static constexpr int OFF_STATS   = STAGES * STAGE_BYTES;     // 122880
static constexpr int SMEM_BYTES  = OFF_STATS + (BM + BN) * 4; // 124416

// ---------------------------------------------------------------------------
// Device scratch
// ---------------------------------------------------------------------------
__device__ __align__(128) int8_t g_Xq[(size_t)B_ROWS * D_DIM];
__device__ __align__(128) int8_t g_Mq[(size_t)S_ROWS * D_DIM];
__device__ float g_av[B_ROWS];   // per-batch affine term
__device__ float g_bv[S_ROWS];   // per-state affine term

// ---------------------------------------------------------------------------
// Helpers
// ---------------------------------------------------------------------------
__device__ __forceinline__ uint32_t smem_u32(const void* p) {
    uint32_t a;
    asm("{ .reg .u64 t; cvta.to.shared.u64 t, %1; cvt.u32.u64 %0, t; }"
        : "=r"(a) : "l"(p));
    return a;
}

__device__ __forceinline__ void cp_async16(uint32_t dst, const void* src) {
    asm volatile("cp.async.cg.shared.global [%0], [%1], 16;" :: "r"(dst), "l"(src));
}

__device__ __forceinline__ void ldmat_x4(uint32_t* r, uint32_t addr) {
    asm volatile("ldmatrix.sync.aligned.m8n8.x4.shared.b16 {%0,%1,%2,%3}, [%4];"
                 : "=r"(r[0]), "=r"(r[1]), "=r"(r[2]), "=r"(r[3]) : "r"(addr));
}

__device__ __forceinline__ void mma_s8(int* c, const uint32_t* a, const uint32_t* b) {
    asm volatile(
        "mma.sync.aligned.m16n8k32.row.col.s32.s8.s8.s32 "
        "{%0,%1,%2,%3}, {%4,%5,%6,%7}, {%8,%9}, {%0,%1,%2,%3};"
        : "+r"(c[0]), "+r"(c[1]), "+r"(c[2]), "+r"(c[3])
        : "r"(a[0]), "r"(a[1]), "r"(a[2]), "r"(a[3]), "r"(b[0]), "r"(b[1]));
}

// ---------------------------------------------------------------------------
// Stage loader: A tile 128x64 s8, B tile 256x64 s8 via cp.async (16B chunks)
// ---------------------------------------------------------------------------
__device__ __forceinline__ void load_stage(uint32_t sbase,
                                           const int8_t* __restrict__ Xt,
                                           const int8_t* __restrict__ Mt,
                                           int tid) {
    {
        int row = tid >> 2, ch = tid & 3;                  // 512 chunks (A)
        cp_async16(sbase + row * ROW_STRIDE + ch * 16,
                   Xt + (size_t)row * D_DIM + ch * 16);
    }
#pragma unroll
    for (int i = 0; i < 2; i++) {                          // 1024 chunks (B)
        int idx = i * NTHREADS + tid;
        int row = idx >> 2, ch = idx & 3;
        cp_async16(sbase + A_ST_BYTES + row * ROW_STRIDE + ch * 16,
                   Mt + (size_t)row * D_DIM + ch * 16);
    }
}

// ---------------------------------------------------------------------------
// Convert: fp32 -> s8 quantized, + exact fp32 sumsq and int rowsum, folded
// into a single per-row affine coefficient.
// ---------------------------------------------------------------------------
static constexpr int ROW_F4 = D_DIM / 4;  // 624

__global__ void __launch_bounds__(256)
convert_all_kernel(const float* __restrict__ X, const float* __restrict__ M) {
    const int b = blockIdx.x;
    const bool isX = (b < B_ROWS);
    const int row  = isX ? b : b - B_ROWS;
    const float4* src = (const float4*)((isX ? X : M) + (size_t)row * D_DIM);
    uint32_t* dst = (uint32_t*)((isX ? g_Xq : g_Mq) + (size_t)row * D_DIM);
    float* coef = isX ? &g_av[row] : &g_bv[row];

    float acc = 0.f;
    int   rs  = 0;
#pragma unroll 3
    for (int i = threadIdx.x; i < ROW_F4; i += 256) {
        float4 v = src[i];
        acc = fmaf(v.x, v.x, acc);
        acc = fmaf(v.y, v.y, acc);
        acc = fmaf(v.z, v.z, acc);
        acc = fmaf(v.w, v.w, acc);
        int q0 = __float2int_rn(v.x * 254.f) - 127;
        int q1 = __float2int_rn(v.y * 254.f) - 127;
        int q2 = __float2int_rn(v.z * 254.f) - 127;
        int q3 = __float2int_rn(v.w * 254.f) - 127;
        rs += q0 + q1 + q2 + q3;
        dst[i] = (uint32_t)(q0 & 0xFF) | ((uint32_t)(q1 & 0xFF) << 8) |
                 ((uint32_t)(q2 & 0xFF) << 16) | ((uint32_t)(q3 & 0xFF) << 24);
    }
#pragma unroll
    for (int o = 16; o > 0; o >>= 1) {
        acc += __shfl_xor_sync(0xffffffffu, acc, o);
        rs  += __shfl_xor_sync(0xffffffffu, rs, o);
    }
    __shared__ float wsum[8];
    __shared__ int   isum[8];
    if ((threadIdx.x & 31) == 0) {
        wsum[threadIdx.x >> 5] = acc;
        isum[threadIdx.x >> 5] = rs;
    }
    __syncthreads();
    if (threadIdx.x == 0) {
        float t = 0.f; int ti = 0;
#pragma unroll
        for (int i = 0; i < 8; i++) { t += wsum[i]; ti += isum[i]; }
        *coef = -t * 0.002f + (float)ti * K_RS + K_C;
    }
}

// ---------------------------------------------------------------------------
// INT8 GEMM + fused epilogue: out[b,s] = a[b] + b[s] + dot * K_DOT
// 512 threads = 16 warps in 4(M) x 4(N); warp tile 32x64.
// ---------------------------------------------------------------------------
__global__ void __launch_bounds__(NTHREADS, 1)
gemm_kernel(float* __restrict__ out) {
    extern __shared__ char smem[];
    const uint32_t smem_base = smem_u32(smem);
    const int tid    = threadIdx.x;
    const int wid    = tid >> 5;
    const int lane   = tid & 31;
    const int warp_m = wid >> 2;          // 0..3
    const int warp_n = wid & 3;           // 0..3
    const int bn     = blockIdx.x;        // 0..7
    const int bm     = blockIdx.y;        // 0..31

    float* a_s = (float*)(smem + OFF_STATS);
    float* b_s = a_s + BM;
    if (tid < BM) a_s[tid] = g_av[bm * BM + tid];
    if (tid < BN) b_s[tid] = g_bv[bn * BN + tid];

    const int8_t* Xbase = g_Xq + (size_t)(bm * BM) * D_DIM;
    const int8_t* Mbase = g_Mq + (size_t)(bn * BN) * D_DIM;

#pragma unroll
    for (int s = 0; s < STAGES - 1; s++) {
        load_stage(smem_base + s * STAGE_BYTES,
                   Xbase + (size_t)s * BK, Mbase + (size_t)s * BK, tid);
        asm volatile("cp.async.commit_group;" ::: "memory");
    }

    int acc[2][8][4];
#pragma unroll
    for (int t = 0; t < 2; t++)
#pragma unroll
        for (int u = 0; u < 8; u++)
#pragma unroll
            for (int j = 0; j < 4; j++) acc[t][u][j] = 0;

    // ldmatrix address components (16B granules; s8-k32 == f16-k16 pattern)
    const int a_row = warp_m * 32 + (lane & 15);
    const int a_sel = (lane >> 4) * 16;
    const int b_grp = lane >> 3;
    const int b_row = warp_n * 64 + ((b_grp >> 1) * 8) + (lane & 7);
    const int b_sel = (b_grp & 1) * 16;

#pragma unroll 1
    for (int kk = 0; kk < KITERS; kk++) {
        asm volatile("cp.async.wait_group 2;" ::: "memory");
        __syncthreads();

        int kn = kk + STAGES - 1;
        if (kn < KITERS) {
            load_stage(smem_base + (kn & 3) * STAGE_BYTES,
                       Xbase + (size_t)kn * BK, Mbase + (size_t)kn * BK, tid);
        }
        asm volatile("cp.async.commit_group;" ::: "memory");

        const uint32_t sA = smem_base + (kk & 3) * STAGE_BYTES;
        const uint32_t sB = sA + A_ST_BYTES;

#pragma unroll
        for (int ks = 0; ks < 2; ks++) {              // two k32 steps per BK=64
            const int koff = ks * 32;                 // bytes
            uint32_t a[2][4], b[8][2];
#pragma unroll
            for (int t = 0; t < 2; t++)
                ldmat_x4(a[t], sA + (a_row + t * 16) * ROW_STRIDE + koff + a_sel);
#pragma unroll
            for (int v = 0; v < 4; v++) {             // 4 x4 loads -> 8 n8 frags
                uint32_t r[4];
                ldmat_x4(r, sB + (b_row + v * 16) * ROW_STRIDE + koff + b_sel);
                b[v * 2 + 0][0] = r[0]; b[v * 2 + 0][1] = r[1];
                b[v * 2 + 1][0] = r[2]; b[v * 2 + 1][1] = r[3];
            }
#pragma unroll
            for (int t = 0; t < 2; t++)
#pragma unroll
                for (int u = 0; u < 8; u++)
                    mma_s8(acc[t][u], a[t], b[u]);
        }
    }

    // ---------------- Epilogue ----------------
    const int g  = lane >> 2;
    const int tg = lane & 3;

#pragma unroll
    for (int t = 0; t < 2; t++) {
        const int r0 = warp_m * 32 + t * 16 + g;
        const float aa = a_s[r0];
        const float ab = a_s[r0 + 8];
        float* o0 = out + (size_t)(bm * BM + r0) * S_ROWS + bn * BN;
        float* o1 = o0 + (size_t)8 * S_ROWS;
#pragma unroll
        for (int u = 0; u < 8; u++) {
            const int col = warp_n * 64 + u * 8 + tg * 2;
            const float m0 = b_s[col], m1 = b_s[col + 1];
            float2 v0, v1;
            v0.x = aa + m0 + (float)acc[t][u][0] * K_DOT;
            v0.y = aa + m1 + (float)acc[t][u][1] * K_DOT;
            v1.x = ab + m0 + (float)acc[t][u][2] * K_DOT;
            v1.y = ab + m1 + (float)acc[t][u][3] * K_DOT;
            *(float2*)(o0 + col) = v0;
            *(float2*)(o1 + col) = v1;
        }
    }
}

// ---------------------------------------------------------------------------
// Launch
// ---------------------------------------------------------------------------
extern "C" void kernel_launch(void* const* d_in, const int* in_sizes, int n_in,
                              void* d_out, int out_size) {
    (void)n_in; (void)out_size;
    const float* X = (const float*)d_in[0];   // observation        [4096, 2496]
    const float* M = (const float*)d_in[1];   // observation_matrix [2048, 2496]
    if (in_sizes[0] == S_ROWS * D_DIM) {      // robust to ordering
        X = (const float*)d_in[1];
        M = (const float*)d_in[0];
    }
    float* out = (float*)d_out;

    cudaFuncSetAttribute(gemm_kernel,
                         cudaFuncAttributeMaxDynamicSharedMemorySize, SMEM_BYTES);

    convert_all_kernel<<<B_ROWS + S_ROWS, 256>>>(X, M);

    dim3 grid(S_ROWS / BN, B_ROWS / BM);  // (8, 32) = 256 CTAs
    gemm_kernel<<<grid, NTHREADS, SMEM_BYTES>>>(out);
}

// round 7
// speedup vs baseline: 2.0825x; 2.0825x over previous
#include <cuda_runtime.h>
#include <cuda_bf16.h>
#include <cstdint>
#include <cstddef>

// ---------------------------------------------------------------------------
// Problem constants
// ---------------------------------------------------------------------------
static constexpr int D_DIM  = 2496;   // 16*13*12
static constexpr int B_ROWS = 4096;
static constexpr int S_ROWS = 2048;
static constexpr float OUT_SCALE = -1.0f / 500.0f;

// GEMM tiling: quarter tiles to kill wave quantization at the HMMA rt=16 wall.
static constexpr int BM = 64;             // batch rows per CTA (M)
static constexpr int BN = 128;            // states per CTA (N)
static constexpr int BK = 32;             // K elems per stage (64 B rows)
static constexpr int KITERS = D_DIM / BK; // 78 exact
static constexpr int STAGES = 4;
static constexpr int NTHREADS = 256;      // 8 warps: 2(M) x 4(N), warp tile 32x32

// Padded smem rows: 64 B data + 16 B pad = 80 B stride (conflict-free).
static constexpr int ROW_STRIDE  = 80;
static constexpr int A_ST_BYTES  = BM * ROW_STRIDE;          // 5120
static constexpr int B_ST_BYTES  = BN * ROW_STRIDE;          // 10240
static constexpr int STAGE_BYTES = A_ST_BYTES + B_ST_BYTES;  // 15360
static constexpr int OFF_STATS   = STAGES * STAGE_BYTES;     // 61440
static constexpr int SMEM_BYTES  = OFF_STATS + (BM + BN) * 4; // 62208

// ---------------------------------------------------------------------------
// Device scratch (allocation-free rule: __device__ globals)
// ---------------------------------------------------------------------------
__device__ __align__(128) __nv_bfloat16 g_Xbf[(size_t)B_ROWS * D_DIM];
__device__ __align__(128) __nv_bfloat16 g_Mbf[(size_t)S_ROWS * D_DIM];
__device__ float g_xsq[B_ROWS];
__device__ float g_msq[S_ROWS];

// ---------------------------------------------------------------------------
// Helpers
// ---------------------------------------------------------------------------
__device__ __forceinline__ uint32_t smem_u32(const void* p) {
    uint32_t a;
    asm("{ .reg .u64 t; cvta.to.shared.u64 t, %1; cvt.u32.u64 %0, t; }"
        : "=r"(a) : "l"(p));
    return a;
}

__device__ __forceinline__ void cp_async16(uint32_t dst, const void* src) {
    asm volatile("cp.async.cg.shared.global [%0], [%1], 16;" :: "r"(dst), "l"(src));
}

__device__ __forceinline__ void ldmat_x4(uint32_t* r, uint32_t addr) {
    asm volatile("ldmatrix.sync.aligned.m8n8.x4.shared.b16 {%0,%1,%2,%3}, [%4];"
                 : "=r"(r[0]), "=r"(r[1]), "=r"(r[2]), "=r"(r[3]) : "r"(addr));
}

__device__ __forceinline__ void mma_bf16(float* c, const uint32_t* a, const uint32_t* b) {
    asm volatile(
        "mma.sync.aligned.m16n8k16.row.col.f32.bf16.bf16.f32 "
        "{%0,%1,%2,%3}, {%4,%5,%6,%7}, {%8,%9}, {%0,%1,%2,%3};"
        : "+f"(c[0]), "+f"(c[1]), "+f"(c[2]), "+f"(c[3])
        : "r"(a[0]), "r"(a[1]), "r"(a[2]), "r"(a[3]), "r"(b[0]), "r"(b[1]));
}

// ---------------------------------------------------------------------------
// Stage loader: A tile 64x32 bf16, B tile 128x32 bf16 via cp.async (16B)
// 256 threads: A = 256 chunks (1/thread), B = 512 chunks (2/thread)
// ---------------------------------------------------------------------------
__device__ __forceinline__ void load_stage(uint32_t sbase,
                                           const __nv_bfloat16* __restrict__ Xt,
                                           const __nv_bfloat16* __restrict__ Mt,
                                           int tid) {
    {
        int row = tid >> 2, ch = tid & 3;
        cp_async16(sbase + row * ROW_STRIDE + ch * 16,
                   Xt + (size_t)row * D_DIM + ch * 8);
    }
#pragma unroll
    for (int i = 0; i < 2; i++) {
        int idx = i * NTHREADS + tid;
        int row = idx >> 2, ch = idx & 3;
        cp_async16(sbase + A_ST_BYTES + row * ROW_STRIDE + ch * 16,
                   Mt + (size_t)row * D_DIM + ch * 8);
    }
}

// ---------------------------------------------------------------------------
// Merged, vectorized conversion: fp32 -> bf16 + exact fp32 row sum-of-squares.
// ---------------------------------------------------------------------------
static constexpr int ROW_F4 = D_DIM / 4;  // 624

__global__ void __launch_bounds__(256)
convert_all_kernel(const float* __restrict__ X, const float* __restrict__ M) {
    const int b = blockIdx.x;
    const bool isX = (b < B_ROWS);
    const int row  = isX ? b : b - B_ROWS;
    const float4* src = (const float4*)((isX ? X : M) + (size_t)row * D_DIM);
    uint2* dst = (uint2*)((isX ? g_Xbf : g_Mbf) + (size_t)row * D_DIM);
    float* sq  = isX ? &g_xsq[row] : &g_msq[row];

    float acc = 0.f;
#pragma unroll 3
    for (int i = threadIdx.x; i < ROW_F4; i += 256) {
        float4 v = src[i];
        acc = fmaf(v.x, v.x, acc);
        acc = fmaf(v.y, v.y, acc);
        acc = fmaf(v.z, v.z, acc);
        acc = fmaf(v.w, v.w, acc);
        __nv_bfloat162 lo = __floats2bfloat162_rn(v.x, v.y);
        __nv_bfloat162 hi = __floats2bfloat162_rn(v.z, v.w);
        uint2 o;
        o.x = *(uint32_t*)&lo;
        o.y = *(uint32_t*)&hi;
        dst[i] = o;
    }
#pragma unroll
    for (int o = 16; o > 0; o >>= 1) acc += __shfl_xor_sync(0xffffffffu, acc, o);
    __shared__ float wsum[8];
    if ((threadIdx.x & 31) == 0) wsum[threadIdx.x >> 5] = acc;
    __syncthreads();
    if (threadIdx.x == 0) {
        float t = 0.f;
#pragma unroll
        for (int i = 0; i < 8; i++) t += wsum[i];
        *sq = t;
    }
}

// ---------------------------------------------------------------------------
// GEMM + fused epilogue: out[b,s] = (xsq[b] + msq[s] - 2*cross) * (-1/500)
// 256 threads = 8 warps in 2(M) x 4(N); warp tile 32x32. 2 CTAs/SM.
// ---------------------------------------------------------------------------
__global__ void __launch_bounds__(NTHREADS, 2)
gemm_kernel(float* __restrict__ out) {
    extern __shared__ char smem[];
    const uint32_t smem_base = smem_u32(smem);
    const int tid    = threadIdx.x;
    const int wid    = tid >> 5;
    const int lane   = tid & 31;
    const int warp_m = wid >> 2;          // 0..1
    const int warp_n = wid & 3;           // 0..3
    const int bn     = blockIdx.x;        // 0..15
    const int bm     = blockIdx.y;        // 0..63

    // Stage row norms into smem (overlaps with cp.async prologue)
    float* xs_s = (float*)(smem + OFF_STATS);
    float* ms_s = xs_s + BM;
    if (tid < BM) xs_s[tid] = g_xsq[bm * BM + tid];
    if (tid < BN) ms_s[tid] = g_msq[bn * BN + tid];

    const __nv_bfloat16* Xbase = g_Xbf + (size_t)(bm * BM) * D_DIM;
    const __nv_bfloat16* Mbase = g_Mbf + (size_t)(bn * BN) * D_DIM;

    // Prologue: fill STAGES-1 stages
#pragma unroll
    for (int s = 0; s < STAGES - 1; s++) {
        load_stage(smem_base + s * STAGE_BYTES,
                   Xbase + (size_t)s * BK, Mbase + (size_t)s * BK, tid);
        asm volatile("cp.async.commit_group;" ::: "memory");
    }

    float acc[2][4][4];
#pragma unroll
    for (int t = 0; t < 2; t++)
#pragma unroll
        for (int u = 0; u < 4; u++)
#pragma unroll
            for (int j = 0; j < 4; j++) acc[t][u][j] = 0.f;

    // Per-lane ldmatrix address components
    const int a_row = warp_m * 32 + (lane & 15);
    const int a_sel = (lane >> 4) * 16;               // bytes (k halves)
    const int b_grp = lane >> 3;                      // 0..3
    const int b_row = warp_n * 32 + ((b_grp >> 1) * 8) + (lane & 7);
    const int b_sel = (b_grp & 1) * 16;               // bytes (k halves)

#pragma unroll 1
    for (int kk = 0; kk < KITERS; kk++) {
        asm volatile("cp.async.wait_group 2;" ::: "memory");
        __syncthreads();

        // Prefetch stage kk+3 into slot (kk+3)&3
        int kn = kk + STAGES - 1;
        if (kn < KITERS) {
            load_stage(smem_base + (kn & 3) * STAGE_BYTES,
                       Xbase + (size_t)kn * BK, Mbase + (size_t)kn * BK, tid);
        }
        asm volatile("cp.async.commit_group;" ::: "memory");

        const uint32_t sA = smem_base + (kk & 3) * STAGE_BYTES;
        const uint32_t sB = sA + A_ST_BYTES;

#pragma unroll
        for (int ks = 0; ks < 2; ks++) {              // two k16 steps per BK=32
            const int koff = ks * 32;                 // bytes
            uint32_t a[2][4], b[4][2];
#pragma unroll
            for (int t = 0; t < 2; t++)
                ldmat_x4(a[t], sA + (a_row + t * 16) * ROW_STRIDE + koff + a_sel);
#pragma unroll
            for (int v = 0; v < 2; v++) {             // 2 x4 loads -> 4 n8 frags
                uint32_t r[4];
                ldmat_x4(r, sB + (b_row + v * 16) * ROW_STRIDE + koff + b_sel);
                b[v * 2 + 0][0] = r[0]; b[v * 2 + 0][1] = r[1];
                b[v * 2 + 1][0] = r[2]; b[v * 2 + 1][1] = r[3];
            }
#pragma unroll
            for (int t = 0; t < 2; t++)
#pragma unroll
                for (int u = 0; u < 4; u++)
                    mma_bf16(acc[t][u], a[t], b[u]);
        }
    }

    // ---------------- Epilogue ----------------
    const int g  = lane >> 2;
    const int tg = lane & 3;

#pragma unroll
    for (int t = 0; t < 2; t++) {
        const int r0 = warp_m * 32 + t * 16 + g;
        const float xsa = xs_s[r0];
        const float xsb = xs_s[r0 + 8];
        float* o0 = out + (size_t)(bm * BM + r0) * S_ROWS + bn * BN;
        float* o1 = o0 + (size_t)8 * S_ROWS;
#pragma unroll
        for (int u = 0; u < 4; u++) {
            const int col = warp_n * 32 + u * 8 + tg * 2;
            const float m0 = ms_s[col], m1 = ms_s[col + 1];
            float2 v0, v1;
            v0.x = (xsa + m0 - 2.f * acc[t][u][0]) * OUT_SCALE;
            v0.y = (xsa + m1 - 2.f * acc[t][u][1]) * OUT_SCALE;
            v1.x = (xsb + m0 - 2.f * acc[t][u][2]) * OUT_SCALE;
            v1.y = (xsb + m1 - 2.f * acc[t][u][3]) * OUT_SCALE;
            *(float2*)(o0 + col) = v0;
            *(float2*)(o1 + col) = v1;
        }
    }
}

// ---------------------------------------------------------------------------
// Launch
// ---------------------------------------------------------------------------
extern "C" void kernel_launch(void* const* d_in, const int* in_sizes, int n_in,
                              void* d_out, int out_size) {
    (void)n_in; (void)out_size;
    const float* X = (const float*)d_in[0];   // observation        [4096, 2496]
    const float* M = (const float*)d_in[1];   // observation_matrix [2048, 2496]
    if (in_sizes[0] == S_ROWS * D_DIM) {      // robust to ordering
        X = (const float*)d_in[1];
        M = (const float*)d_in[0];
    }
    float* out = (float*)d_out;

    cudaFuncSetAttribute(gemm_kernel,
                         cudaFuncAttributeMaxDynamicSharedMemorySize, SMEM_BYTES);

    convert_all_kernel<<<B_ROWS + S_ROWS, 256>>>(X, M);

    dim3 grid(S_ROWS / BN, B_ROWS / BM);  // (16, 64) = 1024 CTAs
    gemm_kernel<<<grid, NTHREADS, SMEM_BYTES>>>(out);
}

// round 8
// speedup vs baseline: 2.1012x; 1.0090x over previous
#include <cuda_runtime.h>
#include <cuda_fp16.h>
#include <cstdint>
#include <cstddef>

// ---------------------------------------------------------------------------
// Problem constants
// ---------------------------------------------------------------------------
static constexpr int D_DIM  = 2496;   // 16*13*12
static constexpr int B_ROWS = 4096;
static constexpr int S_ROWS = 2048;

// Centered formulation: x~ = x - 0.5, m~ = m - 0.5 (sq_dist shift-invariant).
// out = -0.002*|x~|^2 - 0.002*|m~|^2 + 0.004*(x~.m~)
static constexpr float K_CROSS = 0.004f;   // 2/500
static constexpr float K_SQ    = -0.002f;  // -1/500

// GEMM tiling: quarter tiles (wave-tail amortized), fp16 f16-accumulate mma.
static constexpr int BM = 64;
static constexpr int BN = 128;
static constexpr int BK = 32;
static constexpr int KITERS = D_DIM / BK; // 78 exact
static constexpr int STAGES = 4;
static constexpr int NTHREADS = 256;      // 8 warps: 2(M) x 4(N), warp tile 32x32

// Padded smem rows: 64 B data + 16 B pad = 80 B stride (conflict-free).
static constexpr int ROW_STRIDE  = 80;
static constexpr int A_ST_BYTES  = BM * ROW_STRIDE;           // 5120
static constexpr int B_ST_BYTES  = BN * ROW_STRIDE;           // 10240
static constexpr int STAGE_BYTES = A_ST_BYTES + B_ST_BYTES;   // 15360
static constexpr int OFF_STATS   = STAGES * STAGE_BYTES;      // 61440
static constexpr int SMEM_BYTES  = OFF_STATS + (BM + BN) * 4; // 62208

// ---------------------------------------------------------------------------
// Device scratch
// ---------------------------------------------------------------------------
__device__ __align__(128) __half g_Xh[(size_t)B_ROWS * D_DIM];
__device__ __align__(128) __half g_Mh[(size_t)S_ROWS * D_DIM];
__device__ float g_ax[B_ROWS];   // -0.002 * |x~|^2
__device__ float g_bx[S_ROWS];   // -0.002 * |m~|^2

// ---------------------------------------------------------------------------
// Helpers
// ---------------------------------------------------------------------------
__device__ __forceinline__ uint32_t smem_u32(const void* p) {
    uint32_t a;
    asm("{ .reg .u64 t; cvta.to.shared.u64 t, %1; cvt.u32.u64 %0, t; }"
        : "=r"(a) : "l"(p));
    return a;
}

__device__ __forceinline__ void cp_async16(uint32_t dst, const void* src) {
    asm volatile("cp.async.cg.shared.global [%0], [%1], 16;" :: "r"(dst), "l"(src));
}

__device__ __forceinline__ void ldmat_x4(uint32_t* r, uint32_t addr) {
    asm volatile("ldmatrix.sync.aligned.m8n8.x4.shared.b16 {%0,%1,%2,%3}, [%4];"
                 : "=r"(r[0]), "=r"(r[1]), "=r"(r[2]), "=r"(r[3]) : "r"(addr));
}

// fp16 MMA with fp16 accumulator: 2 C registers (4 halves)
__device__ __forceinline__ void mma_f16acc(uint32_t* c, const uint32_t* a,
                                           const uint32_t* b) {
    asm volatile(
        "mma.sync.aligned.m16n8k16.row.col.f16.f16.f16.f16 "
        "{%0,%1}, {%2,%3,%4,%5}, {%6,%7}, {%0,%1};"
        : "+r"(c[0]), "+r"(c[1])
        : "r"(a[0]), "r"(a[1]), "r"(a[2]), "r"(a[3]), "r"(b[0]), "r"(b[1]));
}

// ---------------------------------------------------------------------------
// Stage loader: A tile 64x32 fp16, B tile 128x32 fp16 via cp.async (16B)
// ---------------------------------------------------------------------------
__device__ __forceinline__ void load_stage(uint32_t sbase,
                                           const __half* __restrict__ Xt,
                                           const __half* __restrict__ Mt,
                                           int tid) {
    {
        int row = tid >> 2, ch = tid & 3;
        cp_async16(sbase + row * ROW_STRIDE + ch * 16,
                   Xt + (size_t)row * D_DIM + ch * 8);
    }
#pragma unroll
    for (int i = 0; i < 2; i++) {
        int idx = i * NTHREADS + tid;
        int row = idx >> 2, ch = idx & 3;
        cp_async16(sbase + A_ST_BYTES + row * ROW_STRIDE + ch * 16,
                   Mt + (size_t)row * D_DIM + ch * 8);
    }
}

// ---------------------------------------------------------------------------
// Convert: fp32 -> centered fp16, plus prescaled exact row sum-of-squares.
// ---------------------------------------------------------------------------
static constexpr int ROW_F4 = D_DIM / 4;  // 624

__global__ void __launch_bounds__(256)
convert_all_kernel(const float* __restrict__ X, const float* __restrict__ M) {
    const int b = blockIdx.x;
    const bool isX = (b < B_ROWS);
    const int row  = isX ? b : b - B_ROWS;
    const float4* src = (const float4*)((isX ? X : M) + (size_t)row * D_DIM);
    uint2* dst = (uint2*)((isX ? g_Xh : g_Mh) + (size_t)row * D_DIM);
    float* coef = isX ? &g_ax[row] : &g_bx[row];

    float acc = 0.f;
#pragma unroll 3
    for (int i = threadIdx.x; i < ROW_F4; i += 256) {
        float4 v = src[i];
        float c0 = v.x - 0.5f, c1 = v.y - 0.5f;
        float c2 = v.z - 0.5f, c3 = v.w - 0.5f;
        acc = fmaf(c0, c0, acc);
        acc = fmaf(c1, c1, acc);
        acc = fmaf(c2, c2, acc);
        acc = fmaf(c3, c3, acc);
        __half2 lo = __floats2half2_rn(c0, c1);
        __half2 hi = __floats2half2_rn(c2, c3);
        uint2 o;
        o.x = *(uint32_t*)&lo;
        o.y = *(uint32_t*)&hi;
        dst[i] = o;
    }
#pragma unroll
    for (int o = 16; o > 0; o >>= 1) acc += __shfl_xor_sync(0xffffffffu, acc, o);
    __shared__ float wsum[8];
    if ((threadIdx.x & 31) == 0) wsum[threadIdx.x >> 5] = acc;
    __syncthreads();
    if (threadIdx.x == 0) {
        float t = 0.f;
#pragma unroll
        for (int i = 0; i < 8; i++) t += wsum[i];
        *coef = t * K_SQ;
    }
}

// ---------------------------------------------------------------------------
// GEMM + fused epilogue: out[b,s] = ax[b] + bx[s] + 0.004 * cross
// 256 threads = 8 warps in 2(M) x 4(N); warp tile 32x32. 2 CTAs/SM.
// ---------------------------------------------------------------------------
__global__ void __launch_bounds__(NTHREADS, 2)
gemm_kernel(float* __restrict__ out) {
    extern __shared__ char smem[];
    const uint32_t smem_base = smem_u32(smem);
    const int tid    = threadIdx.x;
    const int wid    = tid >> 5;
    const int lane   = tid & 31;
    const int warp_m = wid >> 2;          // 0..1
    const int warp_n = wid & 3;           // 0..3
    const int bn     = blockIdx.x;        // 0..15
    const int bm     = blockIdx.y;        // 0..63

    float* xs_s = (float*)(smem + OFF_STATS);
    float* ms_s = xs_s + BM;
    if (tid < BM) xs_s[tid] = g_ax[bm * BM + tid];
    if (tid < BN) ms_s[tid] = g_bx[bn * BN + tid];

    const __half* Xbase = g_Xh + (size_t)(bm * BM) * D_DIM;
    const __half* Mbase = g_Mh + (size_t)(bn * BN) * D_DIM;

#pragma unroll
    for (int s = 0; s < STAGES - 1; s++) {
        load_stage(smem_base + s * STAGE_BYTES,
                   Xbase + (size_t)s * BK, Mbase + (size_t)s * BK, tid);
        asm volatile("cp.async.commit_group;" ::: "memory");
    }

    uint32_t acc[2][4][2];
#pragma unroll
    for (int t = 0; t < 2; t++)
#pragma unroll
        for (int u = 0; u < 4; u++) { acc[t][u][0] = 0u; acc[t][u][1] = 0u; }

    const int a_row = warp_m * 32 + (lane & 15);
    const int a_sel = (lane >> 4) * 16;
    const int b_grp = lane >> 3;
    const int b_row = warp_n * 32 + ((b_grp >> 1) * 8) + (lane & 7);
    const int b_sel = (b_grp & 1) * 16;

#pragma unroll 1
    for (int kk = 0; kk < KITERS; kk++) {
        asm volatile("cp.async.wait_group 2;" ::: "memory");
        __syncthreads();

        int kn = kk + STAGES - 1;
        if (kn < KITERS) {
            load_stage(smem_base + (kn & 3) * STAGE_BYTES,
                       Xbase + (size_t)kn * BK, Mbase + (size_t)kn * BK, tid);
        }
        asm volatile("cp.async.commit_group;" ::: "memory");

        const uint32_t sA = smem_base + (kk & 3) * STAGE_BYTES;
        const uint32_t sB = sA + A_ST_BYTES;

#pragma unroll
        for (int ks = 0; ks < 2; ks++) {              // two k16 steps per BK=32
            const int koff = ks * 32;                 // bytes
            uint32_t a[2][4], b[4][2];
#pragma unroll
            for (int t = 0; t < 2; t++)
                ldmat_x4(a[t], sA + (a_row + t * 16) * ROW_STRIDE + koff + a_sel);
#pragma unroll
            for (int v = 0; v < 2; v++) {             // 2 x4 loads -> 4 n8 frags
                uint32_t r[4];
                ldmat_x4(r, sB + (b_row + v * 16) * ROW_STRIDE + koff + b_sel);
                b[v * 2 + 0][0] = r[0]; b[v * 2 + 0][1] = r[1];
                b[v * 2 + 1][0] = r[2]; b[v * 2 + 1][1] = r[3];
            }
#pragma unroll
            for (int t = 0; t < 2; t++)
#pragma unroll
                for (int u = 0; u < 4; u++)
                    mma_f16acc(acc[t][u], a[t], b[u]);
        }
    }

    // ---------------- Epilogue ----------------
    const int g  = lane >> 2;
    const int tg = lane & 3;

#pragma unroll
    for (int t = 0; t < 2; t++) {
        const int r0 = warp_m * 32 + t * 16 + g;
        const float axa = xs_s[r0];
        const float axb = xs_s[r0 + 8];
        float* o0 = out + (size_t)(bm * BM + r0) * S_ROWS + bn * BN;
        float* o1 = o0 + (size_t)8 * S_ROWS;
#pragma unroll
        for (int u = 0; u < 4; u++) {
            const int col = warp_n * 32 + u * 8 + tg * 2;
            const float m0 = ms_s[col], m1 = ms_s[col + 1];
            float2 clo = __half22float2(*(__half2*)&acc[t][u][0]);  // row r0
            float2 chi = __half22float2(*(__half2*)&acc[t][u][1]);  // row r0+8
            float2 v0, v1;
            v0.x = axa + m0 + K_CROSS * clo.x;
            v0.y = axa + m1 + K_CROSS * clo.y;
            v1.x = axb + m0 + K_CROSS * chi.x;
            v1.y = axb + m1 + K_CROSS * chi.y;
            *(float2*)(o0 + col) = v0;
            *(float2*)(o1 + col) = v1;
        }
    }
}

// ---------------------------------------------------------------------------
// Launch
// ---------------------------------------------------------------------------
extern "C" void kernel_launch(void* const* d_in, const int* in_sizes, int n_in,
                              void* d_out, int out_size) {
    (void)n_in; (void)out_size;
    const float* X = (const float*)d_in[0];   // observation        [4096, 2496]
    const float* M = (const float*)d_in[1];   // observation_matrix [2048, 2496]
    if (in_sizes[0] == S_ROWS * D_DIM) {      // robust to ordering
        X = (const float*)d_in[1];
        M = (const float*)d_in[0];
    }
    float* out = (float*)d_out;

    cudaFuncSetAttribute(gemm_kernel,
                         cudaFuncAttributeMaxDynamicSharedMemorySize, SMEM_BYTES);

    convert_all_kernel<<<B_ROWS + S_ROWS, 256>>>(X, M);

    dim3 grid(S_ROWS / BN, B_ROWS / BM);  // (16, 64) = 1024 CTAs
    gemm_kernel<<<grid, NTHREADS, SMEM_BYTES>>>(out);
}